// round 1
// baseline (speedup 1.0000x reference)
#include <cuda_runtime.h>
#include <math.h>

// Problem constants
#define Bdim 2
#define Sdim 2048
#define Hdim 2048
#define NHdim 16
#define Ddim 128
#define FFdim 8192
#define Mrows (Bdim*Sdim)   // 4096

// -------- scratch (device globals; no allocation) --------
__device__ float g_x[(size_t)Mrows*Hdim];        // LN outputs
__device__ float g_qkv[(size_t)Mrows*3*Hdim];    // QKV gemm out
__device__ float g_q[(size_t)Mrows*Hdim];        // [B,NH,S,D]
__device__ float g_k[(size_t)Mrows*Hdim];
__device__ float g_v[(size_t)Mrows*Hdim];
__device__ float g_ctx[(size_t)Mrows*Hdim];      // [B,S,H]
__device__ float g_hidden[(size_t)Mrows*Hdim];   // residual+attn_out
__device__ float g_inter[(size_t)Mrows*FFdim];
__device__ float g_cos[Sdim*64];
__device__ float g_sin[Sdim*64];

// ============================ LayerNorm ============================
__global__ void ln_kernel(const float* __restrict__ in, const float* __restrict__ w,
                          const float* __restrict__ b, float* __restrict__ out) {
    __shared__ float2 red[256];
    int row = blockIdx.x;
    const float* x = in + (size_t)row * Hdim;
    float s = 0.f, ss = 0.f;
    for (int i = threadIdx.x; i < Hdim; i += 256) {
        float v = x[i];
        s += v;
        ss = fmaf(v, v, ss);
    }
    red[threadIdx.x] = make_float2(s, ss);
    __syncthreads();
    for (int o = 128; o > 0; o >>= 1) {
        if (threadIdx.x < o) {
            float2 a = red[threadIdx.x], c = red[threadIdx.x + o];
            red[threadIdx.x] = make_float2(a.x + c.x, a.y + c.y);
        }
        __syncthreads();
    }
    float mean = red[0].x * (1.0f / Hdim);
    float var  = red[0].y * (1.0f / Hdim) - mean * mean;
    float rstd = rsqrtf(var + 1e-5f);
    float* o = out + (size_t)row * Hdim;
    for (int i = threadIdx.x; i < Hdim; i += 256) {
        o[i] = (x[i] - mean) * rstd * w[i] + b[i];
    }
}

// ============================ GEMM: C = A * W^T + bias (+epilogue) ============================
// A: [M,K] row-major, W: [N,K] row-major. EPI: 0 = bias, 1 = bias+GELU(exact), 2 = bias+residual
template<int EPI>
__global__ void __launch_bounds__(256) gemm_kernel(
    const float* __restrict__ A, const float* __restrict__ W,
    const float* __restrict__ bias, const float* __restrict__ res,
    float* __restrict__ C, int M, int N, int K)
{
    const int BM = 128, BN = 128, BK = 8;
    __shared__ float As[BK][BM];
    __shared__ float Bs[BK][BN];
    int tid = threadIdx.x;
    int bm = blockIdx.y * BM, bn = blockIdx.x * BN;
    int lr = tid >> 1;            // 0..127
    int lc = (tid & 1) * 4;       // 0 or 4
    const float* Ap = A + (size_t)(bm + lr) * K + lc;
    const float* Wp = W + (size_t)(bn + lr) * K + lc;

    float acc[8][8];
#pragma unroll
    for (int i = 0; i < 8; i++)
#pragma unroll
        for (int j = 0; j < 8; j++) acc[i][j] = 0.f;

    int tr = (tid >> 4) * 8;      // 0..120
    int tc = (tid & 15) * 8;

    for (int k0 = 0; k0 < K; k0 += BK) {
        float4 av = *(const float4*)(Ap + k0);
        float4 wv = *(const float4*)(Wp + k0);
        __syncthreads();
        As[lc + 0][lr] = av.x; As[lc + 1][lr] = av.y; As[lc + 2][lr] = av.z; As[lc + 3][lr] = av.w;
        Bs[lc + 0][lr] = wv.x; Bs[lc + 1][lr] = wv.y; Bs[lc + 2][lr] = wv.z; Bs[lc + 3][lr] = wv.w;
        __syncthreads();
#pragma unroll
        for (int kk = 0; kk < BK; kk++) {
            float4 a0 = *(const float4*)&As[kk][tr];
            float4 a1 = *(const float4*)&As[kk][tr + 4];
            float4 b0 = *(const float4*)&Bs[kk][tc];
            float4 b1 = *(const float4*)&Bs[kk][tc + 4];
            float ra[8] = {a0.x, a0.y, a0.z, a0.w, a1.x, a1.y, a1.z, a1.w};
            float rb[8] = {b0.x, b0.y, b0.z, b0.w, b1.x, b1.y, b1.z, b1.w};
#pragma unroll
            for (int i = 0; i < 8; i++)
#pragma unroll
                for (int j = 0; j < 8; j++) acc[i][j] = fmaf(ra[i], rb[j], acc[i][j]);
        }
    }

#pragma unroll
    for (int i = 0; i < 8; i++) {
        int m = bm + tr + i;
        size_t base = (size_t)m * N + bn + tc;
#pragma unroll
        for (int j = 0; j < 8; j++) {
            int n = bn + tc + j;
            float v = acc[i][j] + bias[n];
            if (EPI == 1) v = 0.5f * v * (1.0f + erff(v * 0.70710678118654752f));
            if (EPI == 2) v += res[base + j];
            C[base + j] = v;
        }
    }
}

// ============================ RoPE table (double precision trig) ============================
__global__ void rope_table_kernel() {
    int idx = blockIdx.x * blockDim.x + threadIdx.x;
    if (idx >= Sdim * 64) return;
    int s = idx >> 6, i = idx & 63;
    double invf = exp(-(double)i * (9.210340371976184 / 64.0)); // ln(10000)/64
    double th = (double)s * invf;
    g_cos[idx] = (float)cos(th);
    g_sin[idx] = (float)sin(th);
}

// ============================ QKV split + RoPE ============================
// g_qkv row layout per (b,s): NH blocks of [q(128) | k(128) | v(128)]
__global__ void rope_kernel() {
    int row = blockIdx.x;      // b*S + s
    int h = blockIdx.y;
    int d = threadIdx.x;       // 0..127
    int s = row & (Sdim - 1);
    int b = row >> 11;
    const float* src = g_qkv + (size_t)row * (3 * Hdim) + h * (3 * Ddim);
    float q = src[d];
    float k = src[Ddim + d];
    float v = src[2 * Ddim + d];
    int di = d & 63;
    float cs = g_cos[s * 64 + di];
    float sn = g_sin[s * 64 + di];
    float qp, kp;
    if (d < 64) { qp = -src[d + 64];        kp = -src[Ddim + d + 64]; }
    else        { qp =  src[d - 64];        kp =  src[Ddim + d - 64]; }
    size_t oidx = ((size_t)(b * NHdim + h) * Sdim + s) * Ddim + d;
    g_q[oidx] = q * cs + qp * sn;
    g_k[oidx] = k * cs + kp * sn;
    g_v[oidx] = v;
}

// ============================ Flash attention (fp32, causal) ============================
// grid: (S/Br, B*NH), block 256. Br=64 q rows, Bc=32 k cols per inner tile.
#define ATT_BR 64
#define ATT_BC 32
#define ATT_PD 132   // padded D stride (floats), 16B-aligned rows
#define ATT_PS 36    // padded S-tile stride
#define ATTN_SMEM_BYTES ((ATT_BR*ATT_PD + 2*ATT_BC*ATT_PD + ATT_BR*ATT_PS + 3*ATT_BR) * 4)

__global__ void __launch_bounds__(256) attn_kernel() {
    extern __shared__ float sm[];
    float* Qs  = sm;                          // 64*132
    float* Ks  = Qs + ATT_BR * ATT_PD;        // 32*132
    float* Vs  = Ks + ATT_BC * ATT_PD;        // 32*132
    float* Ss  = Vs + ATT_BC * ATT_PD;        // 64*36
    float* m_s = Ss + ATT_BR * ATT_PS;
    float* l_s = m_s + ATT_BR;
    float* sc_s = l_s + ATT_BR;

    int qt = gridDim.x - 1 - blockIdx.x;   // heavy tiles first
    int bh = blockIdx.y;
    int tid = threadIdx.x;
    int ty = tid >> 4, tx = tid & 15;

    const float* Qg = g_q + ((size_t)bh * Sdim + (size_t)qt * ATT_BR) * Ddim;
    const float* Kg = g_k + (size_t)bh * Sdim * Ddim;
    const float* Vg = g_v + (size_t)bh * Sdim * Ddim;

    for (int i = tid * 4; i < ATT_BR * Ddim; i += 1024) {
        float4 v = *(const float4*)(Qg + i);
        int r = i >> 7, c = i & 127;
        float* q = Qs + r * ATT_PD + c;
        q[0] = v.x; q[1] = v.y; q[2] = v.z; q[3] = v.w;
    }
    if (tid < ATT_BR) { m_s[tid] = -INFINITY; l_s[tid] = 0.f; }

    float acc[4][8];
#pragma unroll
    for (int i = 0; i < 4; i++)
#pragma unroll
        for (int j = 0; j < 8; j++) acc[i][j] = 0.f;

    int nkt = 2 * qt + 2;
    for (int kt = 0; kt < nkt; kt++) {
        __syncthreads();
        const float* Kt = Kg + (size_t)kt * ATT_BC * Ddim;
        const float* Vt = Vg + (size_t)kt * ATT_BC * Ddim;
        for (int i = tid * 4; i < ATT_BC * Ddim; i += 1024) {
            float4 kv = *(const float4*)(Kt + i);
            float4 vv = *(const float4*)(Vt + i);
            int r = i >> 7, c = i & 127;
            float* kp = Ks + r * ATT_PD + c;
            kp[0] = kv.x; kp[1] = kv.y; kp[2] = kv.z; kp[3] = kv.w;
            float* vp = Vs + r * ATT_PD + c;
            vp[0] = vv.x; vp[1] = vv.y; vp[2] = vv.z; vp[3] = vv.w;
        }
        __syncthreads();

        // S = Q K^T : thread -> rows ty*4..+3, cols tx*2..+1
        float sa[4][2];
#pragma unroll
        for (int i = 0; i < 4; i++) { sa[i][0] = 0.f; sa[i][1] = 0.f; }
        const float* q0 = Qs + (ty * 4) * ATT_PD;
        const float* k0 = Ks + (tx * 2) * ATT_PD;
        for (int k = 0; k < Ddim; k += 4) {
            float4 b0 = *(const float4*)(k0 + k);
            float4 b1 = *(const float4*)(k0 + ATT_PD + k);
#pragma unroll
            for (int i = 0; i < 4; i++) {
                float4 a = *(const float4*)(q0 + i * ATT_PD + k);
                sa[i][0] += a.x * b0.x + a.y * b0.y + a.z * b0.z + a.w * b0.w;
                sa[i][1] += a.x * b1.x + a.y * b1.y + a.z * b1.z + a.w * b1.w;
            }
        }
        int qbase = qt * ATT_BR + ty * 4;
        int kbase = kt * ATT_BC + tx * 2;
#pragma unroll
        for (int i = 0; i < 4; i++) {
#pragma unroll
            for (int j = 0; j < 2; j++) {
                float v = sa[i][j] * 0.08838834764831845f;  // 1/sqrt(128)
                if (kbase + j > qbase + i) v = -1e30f;
                Ss[(ty * 4 + i) * ATT_PS + tx * 2 + j] = v;
            }
        }
        __syncthreads();

        // online softmax, one thread per row
        if (tid < ATT_BR) {
            float mold = m_s[tid];
            float mnew = mold;
            float* srow = Ss + tid * ATT_PS;
#pragma unroll
            for (int c = 0; c < ATT_BC; c++) mnew = fmaxf(mnew, srow[c]);
            float lsum = 0.f;
#pragma unroll
            for (int c = 0; c < ATT_BC; c++) {
                float p = expf(srow[c] - mnew);
                srow[c] = p;
                lsum += p;
            }
            float scl = expf(mold - mnew);
            sc_s[tid] = scl;
            l_s[tid] = l_s[tid] * scl + lsum;
            m_s[tid] = mnew;
        }
        __syncthreads();

        // O = O*scale + P V : thread -> rows ty*4..+3, dcols tx*8..+7
#pragma unroll
        for (int i = 0; i < 4; i++) {
            float scl = sc_s[ty * 4 + i];
#pragma unroll
            for (int j = 0; j < 8; j++) acc[i][j] *= scl;
        }
        const float* s0 = Ss + (ty * 4) * ATT_PS;
        const float* v0 = Vs + tx * 8;
        for (int c = 0; c < ATT_BC; c += 4) {
            float pr[4][4];
            *(float4*)pr[0] = *(const float4*)(s0 + 0 * ATT_PS + c);
            *(float4*)pr[1] = *(const float4*)(s0 + 1 * ATT_PS + c);
            *(float4*)pr[2] = *(const float4*)(s0 + 2 * ATT_PS + c);
            *(float4*)pr[3] = *(const float4*)(s0 + 3 * ATT_PS + c);
#pragma unroll
            for (int cc = 0; cc < 4; cc++) {
                float4 va = *(const float4*)(v0 + (c + cc) * ATT_PD);
                float4 vb = *(const float4*)(v0 + (c + cc) * ATT_PD + 4);
#pragma unroll
                for (int i = 0; i < 4; i++) {
                    float p = pr[i][cc];
                    acc[i][0] = fmaf(p, va.x, acc[i][0]);
                    acc[i][1] = fmaf(p, va.y, acc[i][1]);
                    acc[i][2] = fmaf(p, va.z, acc[i][2]);
                    acc[i][3] = fmaf(p, va.w, acc[i][3]);
                    acc[i][4] = fmaf(p, vb.x, acc[i][4]);
                    acc[i][5] = fmaf(p, vb.y, acc[i][5]);
                    acc[i][6] = fmaf(p, vb.z, acc[i][6]);
                    acc[i][7] = fmaf(p, vb.w, acc[i][7]);
                }
            }
        }
    }

    // write ctx in [B,S,H] layout
    int b = bh >> 4, h = bh & 15;
#pragma unroll
    for (int i = 0; i < 4; i++) {
        int r = ty * 4 + i;
        int sg = qt * ATT_BR + r;
        float inv = 1.0f / l_s[r];
        float* op = g_ctx + ((size_t)(b * Sdim + sg) * Hdim) + h * Ddim + tx * 8;
#pragma unroll
        for (int j = 0; j < 8; j++) op[j] = acc[i][j] * inv;
    }
}

// ============================ mask passthrough ============================
__global__ void mask_kernel(const unsigned char* __restrict__ m, float* __restrict__ o, int n) {
    int i = blockIdx.x * blockDim.x + threadIdx.x;
    if (i < n) o[i] = m[i] ? 1.0f : 0.0f;
}

// ============================ launch ============================
extern "C" void kernel_launch(void* const* d_in, const int* in_sizes, int n_in,
                              void* d_out, int out_size) {
    const float* hs            = (const float*)d_in[0];
    const unsigned char* mask  = (const unsigned char*)d_in[1];
    const float* ln1w          = (const float*)d_in[2];
    const float* ln1b          = (const float*)d_in[3];
    const float* wqkv          = (const float*)d_in[4];
    const float* bqkv          = (const float*)d_in[5];
    const float* wdense        = (const float*)d_in[6];
    const float* bdense        = (const float*)d_in[7];
    const float* ln2w          = (const float*)d_in[8];
    const float* ln2b          = (const float*)d_in[9];
    const float* w1            = (const float*)d_in[10];
    const float* b1            = (const float*)d_in[11];
    const float* w2            = (const float*)d_in[12];
    const float* b2            = (const float*)d_in[13];
    float* out = (float*)d_out;

    float *px, *pqkv, *pctx, *phid, *pinter;
    cudaGetSymbolAddress((void**)&px,     g_x);
    cudaGetSymbolAddress((void**)&pqkv,   g_qkv);
    cudaGetSymbolAddress((void**)&pctx,   g_ctx);
    cudaGetSymbolAddress((void**)&phid,   g_hidden);
    cudaGetSymbolAddress((void**)&pinter, g_inter);

    cudaFuncSetAttribute(attn_kernel, cudaFuncAttributeMaxDynamicSharedMemorySize,
                         ATTN_SMEM_BYTES);

    // LN1
    ln_kernel<<<Mrows, 256>>>(hs, ln1w, ln1b, px);
    // RoPE trig table
    rope_table_kernel<<<(Sdim * 64) / 256, 256>>>();
    // QKV = x @ wqkv^T + bqkv
    gemm_kernel<0><<<dim3(3 * Hdim / 128, Mrows / 128), 256>>>(
        px, wqkv, bqkv, nullptr, pqkv, Mrows, 3 * Hdim, Hdim);
    // split + rope -> g_q, g_k, g_v in [B,NH,S,D]
    rope_kernel<<<dim3(Mrows, NHdim), 128>>>();
    // flash attention -> g_ctx in [B,S,H]
    attn_kernel<<<dim3(Sdim / ATT_BR, Bdim * NHdim), 256, ATTN_SMEM_BYTES>>>();
    // dense + residual(hidden_states) -> g_hidden
    gemm_kernel<2><<<dim3(Hdim / 128, Mrows / 128), 256>>>(
        pctx, wdense, bdense, hs, phid, Mrows, Hdim, Hdim);
    // LN2
    ln_kernel<<<Mrows, 256>>>(phid, ln2w, ln2b, px);
    // FF1 + exact GELU
    gemm_kernel<1><<<dim3(FFdim / 128, Mrows / 128), 256>>>(
        px, w1, b1, nullptr, pinter, Mrows, FFdim, Hdim);
    // FF2 + residual(g_hidden) -> out
    gemm_kernel<2><<<dim3(Hdim / 128, Mrows / 128), 256>>>(
        pinter, w2, b2, phid, out, Mrows, Hdim, FFdim);
    // if output also carries the attention mask, convert it after hidden
    long long hid_elems = (long long)Mrows * Hdim;           // 8388608
    long long mask_elems = (long long)Sdim * Sdim;           // 4194304
    if ((long long)out_size >= hid_elems + mask_elems) {
        mask_kernel<<<(int)(mask_elems / 256), 256>>>(mask, out + hid_elems, (int)mask_elems);
    }
}

// round 4
// speedup vs baseline: 1.9426x; 1.9426x over previous
#include <cuda_runtime.h>
#include <cuda_fp16.h>
#include <cstdint>
#include <stdint.h>
#include <math.h>

// Problem constants
#define Bdim 2
#define Sdim 2048
#define Hdim 2048
#define NHdim 16
#define Ddim 128
#define FFdim 8192
#define Mrows (Bdim*Sdim)   // 4096

// -------- scratch (device globals; no allocation) --------
__device__ float g_x[(size_t)Mrows*Hdim];        // LN outputs
__device__ float g_qkv[(size_t)Mrows*3*Hdim];    // QKV gemm out
__device__ float g_q[(size_t)Mrows*Hdim];        // [B,NH,S,D]
__device__ float g_k[(size_t)Mrows*Hdim];
__device__ float g_v[(size_t)Mrows*Hdim];
__device__ float g_ctx[(size_t)Mrows*Hdim];      // [B,S,H]
__device__ float g_hidden[(size_t)Mrows*Hdim];   // residual+attn_out
__device__ float g_inter[(size_t)Mrows*FFdim];
__device__ float g_cos[Sdim*64];
__device__ float g_sin[Sdim*64];

// ============================ mma.sync helpers (portable, non-'a') ============================
__device__ __forceinline__ uint32_t smem_u32(const void* p) {
    uint32_t a;
    asm("{ .reg .u64 t; cvta.to.shared.u64 t, %1; cvt.u32.u64 %0, t; }" : "=r"(a) : "l"(p));
    return a;
}
__device__ __forceinline__ void ldsm4(uint32_t* r, uint32_t addr) {
    asm volatile("ldmatrix.sync.aligned.m8n8.x4.shared.b16 {%0,%1,%2,%3}, [%4];"
        : "=r"(r[0]), "=r"(r[1]), "=r"(r[2]), "=r"(r[3]) : "r"(addr));
}
__device__ __forceinline__ void mma16816(float* c, const uint32_t* a, uint32_t b0, uint32_t b1) {
    asm volatile("mma.sync.aligned.m16n8k16.row.col.f32.f16.f16.f32 "
        "{%0,%1,%2,%3}, {%4,%5,%6,%7}, {%8,%9}, {%0,%1,%2,%3};"
        : "+f"(c[0]), "+f"(c[1]), "+f"(c[2]), "+f"(c[3])
        : "r"(a[0]), "r"(a[1]), "r"(a[2]), "r"(a[3]), "r"(b0), "r"(b1));
}

// swizzled smem offset: rows of 64B (32 halfs), 16B chunk XOR (row>>1)&3
__device__ __forceinline__ uint32_t swoff(int row, int chunk) {
    return (uint32_t)(row * 64 + ((chunk ^ ((row >> 1) & 3)) << 4));
}

// fp32 x16 -> fp16 hi/lo (8 packed half2 each)
__device__ __forceinline__ void cvt16(const float* v, uint32_t* hi, uint32_t* lo) {
#pragma unroll
    for (int i = 0; i < 8; i++) {
        __half2 h = __floats2half2_rn(v[2*i], v[2*i+1]);
        float2 hf = __half22float2(h);
        __half2 l = __floats2half2_rn(v[2*i] - hf.x, v[2*i+1] - hf.y);
        hi[i] = *(uint32_t*)&h;
        lo[i] = *(uint32_t*)&l;
    }
}

// ============================ HMMA GEMM: C = A * W^T + bias (+epilogue) ============================
// A: [M,K] fp32 row-major, W: [N,K] fp32 row-major. fp16 hi/lo split, 3 passes.
// EPI: 0 = bias, 1 = bias+GELU(exact), 2 = bias+residual
// smem: 2 stages x (Ah, Al, Wh, Wl) x 8KB = 64KB
#define HM_SMEM (2*4*8192)

template<int EPI>
__global__ void __launch_bounds__(256, 1) hmma_gemm(
    const float* __restrict__ A, const float* __restrict__ W,
    const float* __restrict__ bias, const float* __restrict__ res,
    float* __restrict__ C, int M, int N, int K)
{
    extern __shared__ char sm[];
    uint32_t smb = smem_u32(sm);
    int tid = threadIdx.x;
    int lane = tid & 31, wid = tid >> 5;
    int wm = (wid & 3) * 32;       // warp M offset in tile
    int wn = (wid >> 2) * 64;      // warp N offset in tile
    int bm = blockIdx.y * 128, bn = blockIdx.x * 128;

    // per-thread load coords: row tid/2, 16 floats at col (tid&1)*16
    int lrow = tid >> 1;
    int lcol = (tid & 1) * 16;
    const float* Ap = A + (size_t)(bm + lrow) * K + lcol;
    const float* Wp = W + (size_t)(bn + lrow) * K + lcol;
    int cb = (tid & 1) * 2;        // first 16B chunk this thread writes

    float acc[2][8][4];
#pragma unroll
    for (int i = 0; i < 2; i++)
#pragma unroll
        for (int j = 0; j < 8; j++)
#pragma unroll
            for (int q = 0; q < 4; q++) acc[i][j][q] = 0.f;

    // ldmatrix per-lane address pieces
    int mat = lane >> 3, mr = lane & 7;
    int fr_row = (mat & 1) * 8 + mr;   // row within 16-row tile
    int fr_ch  = mat >> 1;             // chunk (k16 half) within k16 step

    const int NC = K >> 5;             // K chunks of 32

    float av[16], wv[16];
    // prologue: load + convert chunk 0
#pragma unroll
    for (int q = 0; q < 4; q++) {
        *(float4*)&av[q*4] = *(const float4*)(Ap + q*4);
        *(float4*)&wv[q*4] = *(const float4*)(Wp + q*4);
    }
    {
        uint32_t hi[8], lo[8];
        cvt16(av, hi, lo);
        *(uint4*)(sm + 0     + swoff(lrow, cb))   = make_uint4(hi[0],hi[1],hi[2],hi[3]);
        *(uint4*)(sm + 0     + swoff(lrow, cb+1)) = make_uint4(hi[4],hi[5],hi[6],hi[7]);
        *(uint4*)(sm + 8192  + swoff(lrow, cb))   = make_uint4(lo[0],lo[1],lo[2],lo[3]);
        *(uint4*)(sm + 8192  + swoff(lrow, cb+1)) = make_uint4(lo[4],lo[5],lo[6],lo[7]);
        cvt16(wv, hi, lo);
        *(uint4*)(sm + 16384 + swoff(lrow, cb))   = make_uint4(hi[0],hi[1],hi[2],hi[3]);
        *(uint4*)(sm + 16384 + swoff(lrow, cb+1)) = make_uint4(hi[4],hi[5],hi[6],hi[7]);
        *(uint4*)(sm + 24576 + swoff(lrow, cb))   = make_uint4(lo[0],lo[1],lo[2],lo[3]);
        *(uint4*)(sm + 24576 + swoff(lrow, cb+1)) = make_uint4(lo[4],lo[5],lo[6],lo[7]);
    }
    __syncthreads();

    for (int c = 0; c < NC; c++) {
        int s = c & 1;
        uint32_t base = smb + s * 32768;

        // issue gmem loads for next chunk (hidden under MMA)
        if (c + 1 < NC) {
            const float* Ap2 = Ap + (c + 1) * 32;
            const float* Wp2 = Wp + (c + 1) * 32;
#pragma unroll
            for (int q = 0; q < 4; q++) {
                *(float4*)&av[q*4] = *(const float4*)(Ap2 + q*4);
                *(float4*)&wv[q*4] = *(const float4*)(Wp2 + q*4);
            }
        }

        // MMA over this chunk: 2 k16 steps
#pragma unroll
        for (int kk = 0; kk < 2; kk++) {
            uint32_t ah[2][4], al[2][4];   // 2 m16 tiles
            uint32_t bh[4][4], bl[4][4];   // 4 n16 groups
#pragma unroll
            for (int i = 0; i < 2; i++) {
                int row = wm + i*16 + fr_row;
                int ch = kk*2 + fr_ch;
                uint32_t off = swoff(row, ch);
                ldsm4(ah[i], base + 0    + off);
                ldsm4(al[i], base + 8192 + off);
            }
#pragma unroll
            for (int j = 0; j < 4; j++) {
                int row = wn + j*16 + fr_row;
                int ch = kk*2 + fr_ch;
                uint32_t off = swoff(row, ch);
                ldsm4(bh[j], base + 16384 + off);
                ldsm4(bl[j], base + 24576 + off);
            }
#pragma unroll
            for (int i = 0; i < 2; i++) {
#pragma unroll
                for (int jj = 0; jj < 8; jj++) {
                    int g = jj >> 1, h = jj & 1;
                    // B frag for n8 tile: {reg h, reg h+2} of the n16 group
                    mma16816(acc[i][jj], ah[i], bh[g][h], bh[g][h+2]);
                    mma16816(acc[i][jj], ah[i], bl[g][h], bl[g][h+2]);
                    mma16816(acc[i][jj], al[i], bh[g][h], bh[g][h+2]);
                }
            }
        }

        // convert + store next chunk into other stage
        if (c + 1 < NC) {
            char* dst = sm + ((c + 1) & 1) * 32768;
            uint32_t hi[8], lo[8];
            cvt16(av, hi, lo);
            *(uint4*)(dst + 0     + swoff(lrow, cb))   = make_uint4(hi[0],hi[1],hi[2],hi[3]);
            *(uint4*)(dst + 0     + swoff(lrow, cb+1)) = make_uint4(hi[4],hi[5],hi[6],hi[7]);
            *(uint4*)(dst + 8192  + swoff(lrow, cb))   = make_uint4(lo[0],lo[1],lo[2],lo[3]);
            *(uint4*)(dst + 8192  + swoff(lrow, cb+1)) = make_uint4(lo[4],lo[5],lo[6],lo[7]);
            cvt16(wv, hi, lo);
            *(uint4*)(dst + 16384 + swoff(lrow, cb))   = make_uint4(hi[0],hi[1],hi[2],hi[3]);
            *(uint4*)(dst + 16384 + swoff(lrow, cb+1)) = make_uint4(hi[4],hi[5],hi[6],hi[7]);
            *(uint4*)(dst + 24576 + swoff(lrow, cb))   = make_uint4(lo[0],lo[1],lo[2],lo[3]);
            *(uint4*)(dst + 24576 + swoff(lrow, cb+1)) = make_uint4(lo[4],lo[5],lo[6],lo[7]);
        }
        __syncthreads();
    }

    // epilogue: write accumulators
    int tr = lane >> 2;           // 0..7
    int tc = (lane & 3) * 2;      // 0,2,4,6
#pragma unroll
    for (int i = 0; i < 2; i++) {
#pragma unroll
        for (int jj = 0; jj < 8; jj++) {
            int n0 = bn + wn + jj*8 + tc;
            float b0 = bias[n0], b1 = bias[n0+1];
#pragma unroll
            for (int half = 0; half < 2; half++) {
                int m = bm + wm + i*16 + tr + half*8;
                size_t idx = (size_t)m * N + n0;
                float v0 = acc[i][jj][half*2 + 0] + b0;
                float v1 = acc[i][jj][half*2 + 1] + b1;
                if (EPI == 1) {
                    v0 = 0.5f * v0 * (1.0f + erff(v0 * 0.70710678118654752f));
                    v1 = 0.5f * v1 * (1.0f + erff(v1 * 0.70710678118654752f));
                }
                if (EPI == 2) { v0 += res[idx]; v1 += res[idx+1]; }
                float2 o = make_float2(v0, v1);
                *(float2*)(C + idx) = o;
            }
        }
    }
}

// ============================ LayerNorm ============================
__global__ void ln_kernel(const float* __restrict__ in, const float* __restrict__ w,
                          const float* __restrict__ b, float* __restrict__ out) {
    __shared__ float2 red[256];
    int row = blockIdx.x;
    const float* x = in + (size_t)row * Hdim;
    float s = 0.f, ss = 0.f;
    for (int i = threadIdx.x; i < Hdim; i += 256) {
        float v = x[i];
        s += v;
        ss = fmaf(v, v, ss);
    }
    red[threadIdx.x] = make_float2(s, ss);
    __syncthreads();
    for (int o = 128; o > 0; o >>= 1) {
        if (threadIdx.x < o) {
            float2 a = red[threadIdx.x], c = red[threadIdx.x + o];
            red[threadIdx.x] = make_float2(a.x + c.x, a.y + c.y);
        }
        __syncthreads();
    }
    float mean = red[0].x * (1.0f / Hdim);
    float var  = red[0].y * (1.0f / Hdim) - mean * mean;
    float rstd = rsqrtf(var + 1e-5f);
    float* o = out + (size_t)row * Hdim;
    for (int i = threadIdx.x; i < Hdim; i += 256) {
        o[i] = (x[i] - mean) * rstd * w[i] + b[i];
    }
}

// ============================ RoPE table (double precision trig) ============================
__global__ void rope_table_kernel() {
    int idx = blockIdx.x * blockDim.x + threadIdx.x;
    if (idx >= Sdim * 64) return;
    int s = idx >> 6, i = idx & 63;
    double invf = exp(-(double)i * (9.210340371976184 / 64.0)); // ln(10000)/64
    double th = (double)s * invf;
    g_cos[idx] = (float)cos(th);
    g_sin[idx] = (float)sin(th);
}

// ============================ QKV split + RoPE ============================
__global__ void rope_kernel() {
    int row = blockIdx.x;      // b*S + s
    int h = blockIdx.y;
    int d = threadIdx.x;       // 0..127
    int s = row & (Sdim - 1);
    int b = row >> 11;
    const float* src = g_qkv + (size_t)row * (3 * Hdim) + h * (3 * Ddim);
    float q = src[d];
    float k = src[Ddim + d];
    float v = src[2 * Ddim + d];
    int di = d & 63;
    float cs = g_cos[s * 64 + di];
    float sn = g_sin[s * 64 + di];
    float qp, kp;
    if (d < 64) { qp = -src[d + 64];        kp = -src[Ddim + d + 64]; }
    else        { qp =  src[d - 64];        kp =  src[Ddim + d - 64]; }
    size_t oidx = ((size_t)(b * NHdim + h) * Sdim + s) * Ddim + d;
    g_q[oidx] = q * cs + qp * sn;
    g_k[oidx] = k * cs + kp * sn;
    g_v[oidx] = v;
}

// ============================ Flash attention (fp32, causal) ============================
#define ATT_BR 64
#define ATT_BC 32
#define ATT_PD 132
#define ATT_PS 36
#define ATTN_SMEM_BYTES ((ATT_BR*ATT_PD + 2*ATT_BC*ATT_PD + ATT_BR*ATT_PS + 3*ATT_BR) * 4)

__global__ void __launch_bounds__(256) attn_kernel() {
    extern __shared__ float smf[];
    float* Qs  = smf;
    float* Ks  = Qs + ATT_BR * ATT_PD;
    float* Vs  = Ks + ATT_BC * ATT_PD;
    float* Ss  = Vs + ATT_BC * ATT_PD;
    float* m_s = Ss + ATT_BR * ATT_PS;
    float* l_s = m_s + ATT_BR;
    float* sc_s = l_s + ATT_BR;

    int qt = gridDim.x - 1 - blockIdx.x;
    int bh = blockIdx.y;
    int tid = threadIdx.x;
    int ty = tid >> 4, tx = tid & 15;

    const float* Qg = g_q + ((size_t)bh * Sdim + (size_t)qt * ATT_BR) * Ddim;
    const float* Kg = g_k + (size_t)bh * Sdim * Ddim;
    const float* Vg = g_v + (size_t)bh * Sdim * Ddim;

    for (int i = tid * 4; i < ATT_BR * Ddim; i += 1024) {
        float4 v = *(const float4*)(Qg + i);
        int r = i >> 7, c = i & 127;
        float* q = Qs + r * ATT_PD + c;
        q[0] = v.x; q[1] = v.y; q[2] = v.z; q[3] = v.w;
    }
    if (tid < ATT_BR) { m_s[tid] = -INFINITY; l_s[tid] = 0.f; }

    float acc[4][8];
#pragma unroll
    for (int i = 0; i < 4; i++)
#pragma unroll
        for (int j = 0; j < 8; j++) acc[i][j] = 0.f;

    int nkt = 2 * qt + 2;
    for (int kt = 0; kt < nkt; kt++) {
        __syncthreads();
        const float* Kt = Kg + (size_t)kt * ATT_BC * Ddim;
        const float* Vt = Vg + (size_t)kt * ATT_BC * Ddim;
        for (int i = tid * 4; i < ATT_BC * Ddim; i += 1024) {
            float4 kv = *(const float4*)(Kt + i);
            float4 vv = *(const float4*)(Vt + i);
            int r = i >> 7, c = i & 127;
            float* kp = Ks + r * ATT_PD + c;
            kp[0] = kv.x; kp[1] = kv.y; kp[2] = kv.z; kp[3] = kv.w;
            float* vp = Vs + r * ATT_PD + c;
            vp[0] = vv.x; vp[1] = vv.y; vp[2] = vv.z; vp[3] = vv.w;
        }
        __syncthreads();

        float sa[4][2];
#pragma unroll
        for (int i = 0; i < 4; i++) { sa[i][0] = 0.f; sa[i][1] = 0.f; }
        const float* q0 = Qs + (ty * 4) * ATT_PD;
        const float* k0 = Ks + (tx * 2) * ATT_PD;
        for (int k = 0; k < Ddim; k += 4) {
            float4 b0 = *(const float4*)(k0 + k);
            float4 b1 = *(const float4*)(k0 + ATT_PD + k);
#pragma unroll
            for (int i = 0; i < 4; i++) {
                float4 a = *(const float4*)(q0 + i * ATT_PD + k);
                sa[i][0] += a.x * b0.x + a.y * b0.y + a.z * b0.z + a.w * b0.w;
                sa[i][1] += a.x * b1.x + a.y * b1.y + a.z * b1.z + a.w * b1.w;
            }
        }
        int qbase = qt * ATT_BR + ty * 4;
        int kbase = kt * ATT_BC + tx * 2;
#pragma unroll
        for (int i = 0; i < 4; i++) {
#pragma unroll
            for (int j = 0; j < 2; j++) {
                float v = sa[i][j] * 0.08838834764831845f;
                if (kbase + j > qbase + i) v = -1e30f;
                Ss[(ty * 4 + i) * ATT_PS + tx * 2 + j] = v;
            }
        }
        __syncthreads();

        if (tid < ATT_BR) {
            float mold = m_s[tid];
            float mnew = mold;
            float* srow = Ss + tid * ATT_PS;
#pragma unroll
            for (int c = 0; c < ATT_BC; c++) mnew = fmaxf(mnew, srow[c]);
            float lsum = 0.f;
#pragma unroll
            for (int c = 0; c < ATT_BC; c++) {
                float p = expf(srow[c] - mnew);
                srow[c] = p;
                lsum += p;
            }
            float scl = expf(mold - mnew);
            sc_s[tid] = scl;
            l_s[tid] = l_s[tid] * scl + lsum;
            m_s[tid] = mnew;
        }
        __syncthreads();

#pragma unroll
        for (int i = 0; i < 4; i++) {
            float scl = sc_s[ty * 4 + i];
#pragma unroll
            for (int j = 0; j < 8; j++) acc[i][j] *= scl;
        }
        const float* s0 = Ss + (ty * 4) * ATT_PS;
        const float* v0 = Vs + tx * 8;
        for (int c = 0; c < ATT_BC; c += 4) {
            float pr[4][4];
            *(float4*)pr[0] = *(const float4*)(s0 + 0 * ATT_PS + c);
            *(float4*)pr[1] = *(const float4*)(s0 + 1 * ATT_PS + c);
            *(float4*)pr[2] = *(const float4*)(s0 + 2 * ATT_PS + c);
            *(float4*)pr[3] = *(const float4*)(s0 + 3 * ATT_PS + c);
#pragma unroll
            for (int cc = 0; cc < 4; cc++) {
                float4 va = *(const float4*)(v0 + (c + cc) * ATT_PD);
                float4 vb = *(const float4*)(v0 + (c + cc) * ATT_PD + 4);
#pragma unroll
                for (int i = 0; i < 4; i++) {
                    float p = pr[i][cc];
                    acc[i][0] = fmaf(p, va.x, acc[i][0]);
                    acc[i][1] = fmaf(p, va.y, acc[i][1]);
                    acc[i][2] = fmaf(p, va.z, acc[i][2]);
                    acc[i][3] = fmaf(p, va.w, acc[i][3]);
                    acc[i][4] = fmaf(p, vb.x, acc[i][4]);
                    acc[i][5] = fmaf(p, vb.y, acc[i][5]);
                    acc[i][6] = fmaf(p, vb.z, acc[i][6]);
                    acc[i][7] = fmaf(p, vb.w, acc[i][7]);
                }
            }
        }
    }

    int b = bh >> 4, h = bh & 15;
#pragma unroll
    for (int i = 0; i < 4; i++) {
        int r = ty * 4 + i;
        int sg = qt * ATT_BR + r;
        float inv = 1.0f / l_s[r];
        float* op = g_ctx + ((size_t)(b * Sdim + sg) * Hdim) + h * Ddim + tx * 8;
#pragma unroll
        for (int j = 0; j < 8; j++) op[j] = acc[i][j] * inv;
    }
}

// ============================ mask passthrough ============================
__global__ void mask_kernel(const unsigned char* __restrict__ m, float* __restrict__ o, int n) {
    int i = blockIdx.x * blockDim.x + threadIdx.x;
    if (i < n) o[i] = m[i] ? 1.0f : 0.0f;
}

// ============================ launch ============================
extern "C" void kernel_launch(void* const* d_in, const int* in_sizes, int n_in,
                              void* d_out, int out_size) {
    const float* hs            = (const float*)d_in[0];
    const unsigned char* mask  = (const unsigned char*)d_in[1];
    const float* ln1w          = (const float*)d_in[2];
    const float* ln1b          = (const float*)d_in[3];
    const float* wqkv          = (const float*)d_in[4];
    const float* bqkv          = (const float*)d_in[5];
    const float* wdense        = (const float*)d_in[6];
    const float* bdense        = (const float*)d_in[7];
    const float* ln2w          = (const float*)d_in[8];
    const float* ln2b          = (const float*)d_in[9];
    const float* w1            = (const float*)d_in[10];
    const float* b1            = (const float*)d_in[11];
    const float* w2            = (const float*)d_in[12];
    const float* b2            = (const float*)d_in[13];
    float* out = (float*)d_out;

    float *px, *pqkv, *pctx, *phid, *pinter;
    cudaGetSymbolAddress((void**)&px,     g_x);
    cudaGetSymbolAddress((void**)&pqkv,   g_qkv);
    cudaGetSymbolAddress((void**)&pctx,   g_ctx);
    cudaGetSymbolAddress((void**)&phid,   g_hidden);
    cudaGetSymbolAddress((void**)&pinter, g_inter);

    cudaFuncSetAttribute(attn_kernel, cudaFuncAttributeMaxDynamicSharedMemorySize,
                         ATTN_SMEM_BYTES);
    cudaFuncSetAttribute(hmma_gemm<0>, cudaFuncAttributeMaxDynamicSharedMemorySize, HM_SMEM);
    cudaFuncSetAttribute(hmma_gemm<1>, cudaFuncAttributeMaxDynamicSharedMemorySize, HM_SMEM);
    cudaFuncSetAttribute(hmma_gemm<2>, cudaFuncAttributeMaxDynamicSharedMemorySize, HM_SMEM);

    // LN1
    ln_kernel<<<Mrows, 256>>>(hs, ln1w, ln1b, px);
    // RoPE trig table
    rope_table_kernel<<<(Sdim * 64) / 256, 256>>>();
    // QKV = x @ wqkv^T + bqkv
    hmma_gemm<0><<<dim3(3 * Hdim / 128, Mrows / 128), 256, HM_SMEM>>>(
        px, wqkv, bqkv, nullptr, pqkv, Mrows, 3 * Hdim, Hdim);
    // split + rope -> g_q, g_k, g_v in [B,NH,S,D]
    rope_kernel<<<dim3(Mrows, NHdim), 128>>>();
    // flash attention -> g_ctx in [B,S,H]
    attn_kernel<<<dim3(Sdim / ATT_BR, Bdim * NHdim), 256, ATTN_SMEM_BYTES>>>();
    // dense + residual(hidden_states) -> g_hidden
    hmma_gemm<2><<<dim3(Hdim / 128, Mrows / 128), 256, HM_SMEM>>>(
        pctx, wdense, bdense, hs, phid, Mrows, Hdim, Hdim);
    // LN2
    ln_kernel<<<Mrows, 256>>>(phid, ln2w, ln2b, px);
    // FF1 + exact GELU
    hmma_gemm<1><<<dim3(FFdim / 128, Mrows / 128), 256, HM_SMEM>>>(
        px, w1, b1, nullptr, pinter, Mrows, FFdim, Hdim);
    // FF2 + residual(g_hidden) -> out
    hmma_gemm<2><<<dim3(Hdim / 128, Mrows / 128), 256, HM_SMEM>>>(
        pinter, w2, b2, phid, out, Mrows, Hdim, FFdim);
    // if output also carries the attention mask, convert it after hidden
    long long hid_elems = (long long)Mrows * Hdim;           // 8388608
    long long mask_elems = (long long)Sdim * Sdim;           // 4194304
    if ((long long)out_size >= hid_elems + mask_elems) {
        mask_kernel<<<(int)(mask_elems / 256), 256>>>(mask, out + hid_elems, (int)mask_elems);
    }
}